// round 1
// baseline (speedup 1.0000x reference)
#include <cuda_runtime.h>
#include <math.h>

// ---------------- static device scratch (allocation-free rule) ----------------
__device__ float g_w1q[320*192*25];
__device__ float g_w2q[192*192*25];
__device__ float g_w3q[192*192*25];
__device__ float g_w4q[192*3*25];
__device__ float g_b1q[192];
__device__ float g_b2q[192];
__device__ float g_b3q[192];
__device__ float g_b4q[3];
__device__ float g_a0[192*96*96];
__device__ float g_a1[192*192*192];
__device__ float g_a2[192*384*384];
__device__ float g_params[24];

// ---------------- weight/bias quantization: round-half-even ----------------
__global__ void quant_kernel(const float* __restrict__ src, float* __restrict__ dst, int n) {
    int i = blockIdx.x * blockDim.x + threadIdx.x;
    if (i < n) dst[i] = rintf(src[i]);
}

// ---------------- per-stage fixed-point parameters ----------------
__global__ void prep_kernel(const float* __restrict__ relus,
                            const int* __restrict__ dvds,
                            const int* __restrict__ bitsp) {
    if (threadIdx.x == 0 && blockIdx.x == 0) {
        float B = bitsp ? (float)(*bitsp) : 8.0f;
        float maxv = exp2f(B) - 1.0f;                  // 255
        const int sks[3] = {3, 4, 3};
        for (int i = 0; i < 3; i++) {
            float dv = (float)dvds[i];
            g_params[i*6+0] = exp2f(dv - 10.0f);               // addA = 2^(dv-1-9)
            g_params[i*6+1] = exp2f(9.0f - dv);                // invA = 2^-(dv-9)
            g_params[i*6+2] = rintf((maxv / relus[i]) * 33554432.0f); // clp
            float sk = (float)sks[i];
            g_params[i*6+3] = floorf((relus[i] + exp2f(sk - 1.0f)) * exp2f(-sk)); // scl
            g_params[i*6+4] = exp2f(24.0f - sk);               // addB = 2^(15+9-sk)
            g_params[i*6+5] = exp2f(sk - 25.0f);               // invB = 2^-(16+9-sk)
        }
        float dv3 = (float)dvds[3];
        g_params[18] = exp2f(dv3 - 9.0f);                      // stage3 addA
        g_params[19] = exp2f(8.0f - dv3);                      // stage3 invA
    }
}

// ---------------- universal transposed-conv (k=5,s=2,p=2,op=1) + quant epilogue ----
// Gather form: out(2y+py, 2x+px) = sum_ci sum_{dy,dx} in(y+dy, x+dx) * W[ci][co][py+2-2dy][px+2-2dx]
// Block: 8 warps (co) x 32 lanes (x), 4 input rows per block. 16 accumulators/thread.
__global__ void __launch_bounds__(256, 2) deconv_kernel(
    const float* __restrict__ in, float* __restrict__ out,
    const float* __restrict__ wq, const float* __restrict__ bq,
    const float* __restrict__ mul,
    int CIN, int COUT, int H, int W, int stage)
{
    __shared__ float sIn[8][6][34];
    __shared__ float sW[8][8][25];

    const int tid  = threadIdx.x;
    const int lane = tid & 31;
    const int wid  = tid >> 5;
    const int x0   = blockIdx.x * 32;
    const int y0   = blockIdx.y * 4;
    const int co   = blockIdx.z * 8 + wid;
    const int HW   = H * W;

    float acc[4][4];
    #pragma unroll
    for (int i = 0; i < 4; i++)
        #pragma unroll
        for (int j = 0; j < 4; j++) acc[i][j] = 0.f;

    for (int cib = 0; cib < CIN; cib += 8) {
        __syncthreads();
        // stage input tile (rows y0-1..y0+4, cols x0-1..x0+32), OOB -> 0
        for (int idx = tid; idx < 8*6*34; idx += 256) {
            int ci  = idx / 204;
            int rem = idx - ci * 204;
            int r   = rem / 34;
            int c   = rem - r * 34;
            int gy  = y0 - 1 + r;
            int gx  = x0 - 1 + c;
            float v = 0.f;
            if ((unsigned)gy < (unsigned)H && (unsigned)gx < (unsigned)W)
                v = in[(size_t)(cib + ci) * HW + (size_t)gy * W + gx];
            sIn[ci][r][c] = v;
        }
        // stage weights [ci][co_local][25]
        for (int idx = tid; idx < 8*8*25; idx += 256) {
            int ci  = idx / 200;
            int rem = idx - ci * 200;
            int c8  = rem / 25;
            int t   = rem - c8 * 25;
            int gco = blockIdx.z * 8 + c8;
            sW[ci][c8][t] = (gco < COUT)
                ? wq[((size_t)(cib + ci) * COUT + gco) * 25 + t] : 0.f;
        }
        __syncthreads();

        if (co < COUT) {
            #pragma unroll
            for (int ci = 0; ci < 8; ci++) {
                float wr[25];
                #pragma unroll
                for (int t = 0; t < 25; t++) wr[t] = sW[ci][wid][t];

                float a00 = sIn[ci][0][lane], a01 = sIn[ci][0][lane+1], a02 = sIn[ci][0][lane+2];
                float a10 = sIn[ci][1][lane], a11 = sIn[ci][1][lane+1], a12 = sIn[ci][1][lane+2];
                float a20 = sIn[ci][2][lane], a21 = sIn[ci][2][lane+1], a22 = sIn[ci][2][lane+2];

                #pragma unroll
                for (int yy = 0; yy < 4; yy++) {
                    if (yy) {
                        a00 = a10; a01 = a11; a02 = a12;
                        a10 = a20; a11 = a21; a12 = a22;
                        a20 = sIn[ci][yy+2][lane];
                        a21 = sIn[ci][yy+2][lane+1];
                        a22 = sIn[ci][yy+2][lane+2];
                    }
                    // (py=0,px=0): 9 taps
                    acc[yy][0] += a00*wr[24] + a01*wr[22] + a02*wr[20]
                                + a10*wr[14] + a11*wr[12] + a12*wr[10]
                                + a20*wr[4]  + a21*wr[2]  + a22*wr[0];
                    // (py=0,px=1): 6 taps
                    acc[yy][1] += a01*wr[23] + a02*wr[21]
                                + a11*wr[13] + a12*wr[11]
                                + a21*wr[3]  + a22*wr[1];
                    // (py=1,px=0): 6 taps
                    acc[yy][2] += a10*wr[19] + a11*wr[17] + a12*wr[15]
                                + a20*wr[9]  + a21*wr[7]  + a22*wr[5];
                    // (py=1,px=1): 4 taps
                    acc[yy][3] += a11*wr[18] + a12*wr[16]
                                + a21*wr[8]  + a22*wr[6];
                }
            }
        }
    }

    const int x = x0 + lane;
    if (co >= COUT || x >= W) return;

    const float bias = bq[co];
    const float m    = mul[co];
    float addA, invA, clpv = 0.f, sclv = 0.f, addB = 0.f, invB = 0.f;
    if (stage < 3) {
        addA = g_params[stage*6+0]; invA = g_params[stage*6+1];
        clpv = g_params[stage*6+2]; sclv = g_params[stage*6+3];
        addB = g_params[stage*6+4]; invB = g_params[stage*6+5];
    } else {
        addA = g_params[18]; invA = g_params[19];
    }
    const int OW = 2 * W;
    #pragma unroll
    for (int yy = 0; yy < 4; yy++) {
        int oy = 2 * (y0 + yy);
        #pragma unroll
        for (int q = 0; q < 4; q++) {
            int py = q >> 1, px = q & 1;
            float v = acc[yy][q] + bias;
            v = v * m;
            v = floorf((v + addA) * invA);
            if (stage < 3) {
                v = fminf(fmaxf(v, 0.f), clpv);
                v = floorf((v * sclv + addB) * invB);
            } else {
                v = v / 255.0f;
            }
            out[(size_t)co * (4 * HW) + (size_t)(oy + py) * OW + (2 * x + px)] = v;
        }
    }
}

// ---------------- host launcher (graph-capturable: kernel launches only) -------
extern "C" void kernel_launch(void* const* d_in, const int* in_sizes, int n_in,
                              void* d_out, int out_size)
{
    const float* x     = (const float*)d_in[0];
    const float* w1    = (const float*)d_in[1];
    const float* b1    = (const float*)d_in[2];
    const float* w2    = (const float*)d_in[3];
    const float* b2    = (const float*)d_in[4];
    const float* w3    = (const float*)d_in[5];
    const float* b3    = (const float*)d_in[6];
    const float* w4    = (const float*)d_in[7];
    const float* b4    = (const float*)d_in[8];
    const float* m0    = (const float*)d_in[9];
    const float* m1    = (const float*)d_in[10];
    const float* m2    = (const float*)d_in[11];
    const float* m3    = (const float*)d_in[12];
    const float* relus = (const float*)d_in[13];
    const int*   dvds  = (const int*)d_in[14];
    const int*   bitsp = (n_in > 15) ? (const int*)d_in[15] : nullptr;

    float *w1q, *w2q, *w3q, *w4q, *b1q, *b2q, *b3q, *b4q, *a0, *a1, *a2;
    cudaGetSymbolAddress((void**)&w1q, g_w1q);
    cudaGetSymbolAddress((void**)&w2q, g_w2q);
    cudaGetSymbolAddress((void**)&w3q, g_w3q);
    cudaGetSymbolAddress((void**)&w4q, g_w4q);
    cudaGetSymbolAddress((void**)&b1q, g_b1q);
    cudaGetSymbolAddress((void**)&b2q, g_b2q);
    cudaGetSymbolAddress((void**)&b3q, g_b3q);
    cudaGetSymbolAddress((void**)&b4q, g_b4q);
    cudaGetSymbolAddress((void**)&a0,  g_a0);
    cudaGetSymbolAddress((void**)&a1,  g_a1);
    cudaGetSymbolAddress((void**)&a2,  g_a2);

    auto q = [](const float* s, float* d, int n) {
        quant_kernel<<<(n + 255) / 256, 256>>>(s, d, n);
    };
    q(w1, w1q, 320*192*25);
    q(w2, w2q, 192*192*25);
    q(w3, w3q, 192*192*25);
    q(w4, w4q, 192*3*25);
    q(b1, b1q, 192);
    q(b2, b2q, 192);
    q(b3, b3q, 192);
    q(b4, b4q, 3);
    prep_kernel<<<1, 1>>>(relus, dvds, bitsp);

    // L1: 320ch 48x48 -> 192ch 96x96
    deconv_kernel<<<dim3(2, 12, 24), 256>>>(x,  a0, w1q, b1q, m0, 320, 192,  48,  48, 0);
    // L2: 192ch 96x96 -> 192ch 192x192
    deconv_kernel<<<dim3(3, 24, 24), 256>>>(a0, a1, w2q, b2q, m1, 192, 192,  96,  96, 1);
    // L3: 192ch 192x192 -> 192ch 384x384
    deconv_kernel<<<dim3(6, 48, 24), 256>>>(a1, a2, w3q, b3q, m2, 192, 192, 192, 192, 2);
    // L4: 192ch 384x384 -> 3ch 768x768 (final quant + /255)
    deconv_kernel<<<dim3(12, 96, 1), 256>>>(a2, (float*)d_out, w4q, b4q, m3, 192, 3, 384, 384, 3);
}

// round 2
// speedup vs baseline: 1.2766x; 1.2766x over previous
#include <cuda_runtime.h>
#include <math.h>

// ---------------- static device scratch (allocation-free rule) ----------------
__device__ float g_w1q[320*192*25];
__device__ float g_w2q[192*192*25];
__device__ float g_w3q[192*192*25];
__device__ float g_w4q[192*3*25];
__device__ float g_b1q[192];
__device__ float g_b2q[192];
__device__ float g_b3q[192];
__device__ float g_b4q[3];
__device__ float g_a0[192*96*96];
__device__ float g_a1[192*192*192];
__device__ float g_a2[192*384*384];
__device__ float g_params[24];

// ---------------- weight/bias quantization: round-half-even ----------------
__global__ void quant_kernel(const float* __restrict__ src, float* __restrict__ dst, int n) {
    int i = blockIdx.x * blockDim.x + threadIdx.x;
    if (i < n) dst[i] = rintf(src[i]);
}

// ---------------- per-stage fixed-point parameters ----------------
__global__ void prep_kernel(const float* __restrict__ relus,
                            const int* __restrict__ dvds,
                            const int* __restrict__ bitsp) {
    if (threadIdx.x == 0 && blockIdx.x == 0) {
        float B = bitsp ? (float)(*bitsp) : 8.0f;
        float maxv = exp2f(B) - 1.0f;                  // 255
        const int sks[3] = {3, 4, 3};
        for (int i = 0; i < 3; i++) {
            float dv = (float)dvds[i];
            g_params[i*6+0] = exp2f(dv - 10.0f);               // addA = 2^(dv-1-9)
            g_params[i*6+1] = exp2f(9.0f - dv);                // invA = 2^-(dv-9)
            g_params[i*6+2] = rintf((maxv / relus[i]) * 33554432.0f); // clp
            float sk = (float)sks[i];
            g_params[i*6+3] = floorf((relus[i] + exp2f(sk - 1.0f)) * exp2f(-sk)); // scl
            g_params[i*6+4] = exp2f(24.0f - sk);               // addB = 2^(15+9-sk)
            g_params[i*6+5] = exp2f(sk - 25.0f);               // invB = 2^-(16+9-sk)
        }
        float dv3 = (float)dvds[3];
        g_params[18] = exp2f(dv3 - 9.0f);                      // stage3 addA
        g_params[19] = exp2f(8.0f - dv3);                      // stage3 invA
    }
}

// ---------------- universal transposed-conv (k=5,s=2,p=2,op=1) + quant epilogue ----
// Gather form: out(2y+py, 2x+px) = sum_ci sum_{dy,dx} in(y+dy, x+dx) * W[ci][co][py+2-2dy][px+2-2dx]
// Block: 8 warps; warp = (co_local, ysub). Block covers 8 input rows x 32 input cols.
// COPB = output channels per block, NYSUB = y-subtiles per block (COPB*NYSUB == 8).
template<int COPB, int NYSUB>
__global__ void __launch_bounds__(256, 2) deconv_kernel(
    const float* __restrict__ in, float* __restrict__ out,
    const float* __restrict__ wq, const float* __restrict__ bq,
    const float* __restrict__ mul,
    int CIN, int COUT, int H, int W, int stage)
{
    constexpr int YPW = 8 / NYSUB;               // input rows per warp
    __shared__ float sIn[8][10][34];             // 8 ci x (8+2 halo rows) x (32+2 halo cols)
    __shared__ __align__(16) float sW[8][COPB][28];  // 25 taps padded to 28 (16B-aligned)

    const int tid  = threadIdx.x;
    const int lane = tid & 31;
    const int wid  = tid >> 5;
    const int co_local = wid % COPB;
    const int ysub     = wid / COPB;
    const int x0   = blockIdx.x * 32;
    const int y0   = blockIdx.y * 8;
    const int co   = blockIdx.z * COPB + co_local;
    const int HW   = H * W;

    float acc[YPW][4];
    #pragma unroll
    for (int i = 0; i < YPW; i++)
        #pragma unroll
        for (int j = 0; j < 4; j++) acc[i][j] = 0.f;

    for (int cib = 0; cib < CIN; cib += 8) {
        __syncthreads();
        // stage input tile (rows y0-1..y0+8, cols x0-1..x0+32), OOB -> 0
        for (int idx = tid; idx < 8*10*34; idx += 256) {
            int ci  = idx / 340;
            int rem = idx - ci * 340;
            int r   = rem / 34;
            int c   = rem - r * 34;
            int gy  = y0 - 1 + r;
            int gx  = x0 - 1 + c;
            float v = 0.f;
            if ((unsigned)gy < (unsigned)H && (unsigned)gx < (unsigned)W)
                v = in[(size_t)(cib + ci) * HW + (size_t)gy * W + gx];
            sIn[ci][r][c] = v;
        }
        // stage weights [ci][co_local][25]
        for (int idx = tid; idx < 8*COPB*25; idx += 256) {
            int ci  = idx / (COPB*25);
            int rem = idx - ci * (COPB*25);
            int c8  = rem / 25;
            int t   = rem - c8 * 25;
            int gco = blockIdx.z * COPB + c8;
            sW[ci][c8][t] = (gco < COUT)
                ? wq[((size_t)(cib + ci) * COUT + gco) * 25 + t] : 0.f;
        }
        __syncthreads();

        if (co < COUT) {
            const int base = ysub * YPW;
            for (int ci = 0; ci < 8; ci++) {      // rolled: keeps I-footprint small
                const float4* wv = reinterpret_cast<const float4*>(&sW[ci][co_local][0]);
                float4 q0 = wv[0], q1 = wv[1], q2 = wv[2], q3 = wv[3], q4 = wv[4], q5 = wv[5];
                float wr[25] = {q0.x,q0.y,q0.z,q0.w, q1.x,q1.y,q1.z,q1.w,
                                q2.x,q2.y,q2.z,q2.w, q3.x,q3.y,q3.z,q3.w,
                                q4.x,q4.y,q4.z,q4.w, q5.x,q5.y,q5.z,q5.w,
                                sW[ci][co_local][24]};

                float a00 = sIn[ci][base+0][lane], a01 = sIn[ci][base+0][lane+1], a02 = sIn[ci][base+0][lane+2];
                float a10 = sIn[ci][base+1][lane], a11 = sIn[ci][base+1][lane+1], a12 = sIn[ci][base+1][lane+2];
                float a20 = sIn[ci][base+2][lane], a21 = sIn[ci][base+2][lane+1], a22 = sIn[ci][base+2][lane+2];

                #pragma unroll
                for (int yy = 0; yy < YPW; yy++) {
                    if (yy) {
                        a00 = a10; a01 = a11; a02 = a12;
                        a10 = a20; a11 = a21; a12 = a22;
                        a20 = sIn[ci][base+yy+2][lane];
                        a21 = sIn[ci][base+yy+2][lane+1];
                        a22 = sIn[ci][base+yy+2][lane+2];
                    }
                    // (py=0,px=0): 9 taps
                    acc[yy][0] += a00*wr[24] + a01*wr[22] + a02*wr[20]
                                + a10*wr[14] + a11*wr[12] + a12*wr[10]
                                + a20*wr[4]  + a21*wr[2]  + a22*wr[0];
                    // (py=0,px=1): 6 taps
                    acc[yy][1] += a01*wr[23] + a02*wr[21]
                                + a11*wr[13] + a12*wr[11]
                                + a21*wr[3]  + a22*wr[1];
                    // (py=1,px=0): 6 taps
                    acc[yy][2] += a10*wr[19] + a11*wr[17] + a12*wr[15]
                                + a20*wr[9]  + a21*wr[7]  + a22*wr[5];
                    // (py=1,px=1): 4 taps
                    acc[yy][3] += a11*wr[18] + a12*wr[16]
                                + a21*wr[8]  + a22*wr[6];
                }
            }
        }
    }

    if (co >= COUT) return;
    const int x = x0 + lane;

    const float bias = bq[co];
    const float m    = mul[co];
    float addA, invA, clpv = 0.f, sclv = 0.f, addB = 0.f, invB = 0.f;
    if (stage < 3) {
        addA = g_params[stage*6+0]; invA = g_params[stage*6+1];
        clpv = g_params[stage*6+2]; sclv = g_params[stage*6+3];
        addB = g_params[stage*6+4]; invB = g_params[stage*6+5];
    } else {
        addA = g_params[18]; invA = g_params[19];
    }
    const int OW = 2 * W;
    #pragma unroll
    for (int yy = 0; yy < YPW; yy++) {
        int oy = 2 * (y0 + ysub * YPW + yy);
        #pragma unroll
        for (int q = 0; q < 4; q++) {
            int py = q >> 1, px = q & 1;
            float v = acc[yy][q] + bias;
            v = v * m;
            v = floorf((v + addA) * invA);
            if (stage < 3) {
                v = fminf(fmaxf(v, 0.f), clpv);
                v = floorf((v * sclv + addB) * invB);
            } else {
                v = v / 255.0f;
            }
            out[(size_t)co * (4 * HW) + (size_t)(oy + py) * OW + (2 * x + px)] = v;
        }
    }
}

// ---------------- host launcher (graph-capturable: kernel launches only) -------
extern "C" void kernel_launch(void* const* d_in, const int* in_sizes, int n_in,
                              void* d_out, int out_size)
{
    const float* x     = (const float*)d_in[0];
    const float* w1    = (const float*)d_in[1];
    const float* b1    = (const float*)d_in[2];
    const float* w2    = (const float*)d_in[3];
    const float* b2    = (const float*)d_in[4];
    const float* w3    = (const float*)d_in[5];
    const float* b3    = (const float*)d_in[6];
    const float* w4    = (const float*)d_in[7];
    const float* b4    = (const float*)d_in[8];
    const float* m0    = (const float*)d_in[9];
    const float* m1    = (const float*)d_in[10];
    const float* m2    = (const float*)d_in[11];
    const float* m3    = (const float*)d_in[12];
    const float* relus = (const float*)d_in[13];
    const int*   dvds  = (const int*)d_in[14];
    const int*   bitsp = (n_in > 15) ? (const int*)d_in[15] : nullptr;

    float *w1q, *w2q, *w3q, *w4q, *b1q, *b2q, *b3q, *b4q, *a0, *a1, *a2;
    cudaGetSymbolAddress((void**)&w1q, g_w1q);
    cudaGetSymbolAddress((void**)&w2q, g_w2q);
    cudaGetSymbolAddress((void**)&w3q, g_w3q);
    cudaGetSymbolAddress((void**)&w4q, g_w4q);
    cudaGetSymbolAddress((void**)&b1q, g_b1q);
    cudaGetSymbolAddress((void**)&b2q, g_b2q);
    cudaGetSymbolAddress((void**)&b3q, g_b3q);
    cudaGetSymbolAddress((void**)&b4q, g_b4q);
    cudaGetSymbolAddress((void**)&a0,  g_a0);
    cudaGetSymbolAddress((void**)&a1,  g_a1);
    cudaGetSymbolAddress((void**)&a2,  g_a2);

    auto q = [](const float* s, float* d, int n) {
        quant_kernel<<<(n + 255) / 256, 256>>>(s, d, n);
    };
    q(w1, w1q, 320*192*25);
    q(w2, w2q, 192*192*25);
    q(w3, w3q, 192*192*25);
    q(w4, w4q, 192*3*25);
    q(b1, b1q, 192);
    q(b2, b2q, 192);
    q(b3, b3q, 192);
    q(b4, b4q, 3);
    prep_kernel<<<1, 1>>>(relus, dvds, bitsp);

    // L1: 320ch 48x48 -> 192ch 96x96
    deconv_kernel<8,1><<<dim3(2, 6, 24), 256>>>(x,  a0, w1q, b1q, m0, 320, 192,  48,  48, 0);
    // L2: 192ch 96x96 -> 192ch 192x192
    deconv_kernel<8,1><<<dim3(3, 12, 24), 256>>>(a0, a1, w2q, b2q, m1, 192, 192,  96,  96, 1);
    // L3: 192ch 192x192 -> 192ch 384x384
    deconv_kernel<8,1><<<dim3(6, 24, 24), 256>>>(a1, a2, w3q, b3q, m2, 192, 192, 192, 192, 2);
    // L4: 192ch 384x384 -> 3ch 768x768 (final quant + /255), 4 co-slots x 2 y-subtiles
    deconv_kernel<4,2><<<dim3(12, 48, 1), 256>>>(a2, (float*)d_out, w4q, b4q, m3, 192, 3, 384, 384, 3);
}